// round 3
// baseline (speedup 1.0000x reference)
#include <cuda_runtime.h>
#include <math.h>

#define NT   2048      // B*T tokens
#define DD   1024      // model dim
#define EE   16        // experts
#define FF   512       // expert ffn dim
#define FSH  2048      // shared expert ffn dim

// ---------------- scratch (static device globals; no runtime allocation) ----------------
__device__ int   g_cnt[EE];
__device__ float g_load[EE];
__device__ int   g_tok[EE * NT];
__device__ float g_wt[EE * NT];
__device__ float g_gs[NT];
__device__ float g_H[(size_t)EE * NT * FF];   // expert hidden, per-expert packed rows
__device__ float g_Hs[(size_t)NT * FSH];      // shared-expert hidden

// ---------------------------------------------------------------------------------------
__global__ void zero_k() {
    int i = threadIdx.x;
    if (i < EE) { g_cnt[i] = 0; g_load[i] = 0.f; }
}

// Router: one block (128 thr) per token. Warp-shuffle reduction for logits + gate.
__global__ __launch_bounds__(128) void router_k(const float* __restrict__ x,
                                                const float* __restrict__ rw,
                                                const float* __restrict__ sgw) {
    const int t   = blockIdx.x;
    const int tid = threadIdx.x;
    const float* xr = x + (size_t)t * DD;

    float acc[EE];
#pragma unroll
    for (int e = 0; e < EE; e++) acc[e] = 0.f;
    float gacc = 0.f;

    for (int d = tid; d < DD; d += 128) {
        float xv = xr[d];
        const float* w = rw + (size_t)d * EE;
#pragma unroll
        for (int e = 0; e < EE; e++) acc[e] = fmaf(xv, w[e], acc[e]);
        gacc = fmaf(xv, sgw[d], gacc);
    }

#pragma unroll
    for (int off = 16; off > 0; off >>= 1) {
#pragma unroll
        for (int e = 0; e < EE; e++) acc[e] += __shfl_xor_sync(0xFFFFFFFFu, acc[e], off);
        gacc += __shfl_xor_sync(0xFFFFFFFFu, gacc, off);
    }

    __shared__ float sacc[4][EE];
    __shared__ float sg[4];
    const int w = tid >> 5, l = tid & 31;
    if (l == 0) {
#pragma unroll
        for (int e = 0; e < EE; e++) sacc[w][e] = acc[e];
        sg[w] = gacc;
    }
    __syncthreads();

    if (tid == 0) {
        float p[EE];
        float mx = -1e30f;
#pragma unroll
        for (int e = 0; e < EE; e++) {
            p[e] = sacc[0][e] + sacc[1][e] + sacc[2][e] + sacc[3][e];
            mx = fmaxf(mx, p[e]);
        }
        float s = 0.f;
#pragma unroll
        for (int e = 0; e < EE; e++) { p[e] = expf(p[e] - mx); s += p[e]; }
        float inv = 1.f / s;
#pragma unroll
        for (int e = 0; e < EE; e++) { p[e] *= inv; atomicAdd(&g_load[e], p[e]); }

        int i1 = 0;
#pragma unroll
        for (int e = 1; e < EE; e++) if (p[e] > p[i1]) i1 = e;
        int i2 = (i1 == 0) ? 1 : 0;
#pragma unroll
        for (int e = 0; e < EE; e++) if (e != i1 && p[e] > p[i2]) i2 = e;

        float ws = fmaxf(p[i1] + p[i2], 1e-9f);
        float w1 = p[i1] / ws, w2 = p[i2] / ws;

        int q1 = atomicAdd(&g_cnt[i1], 1);
        g_tok[i1 * NT + q1] = t; g_wt[i1 * NT + q1] = w1;
        int q2 = atomicAdd(&g_cnt[i2], 1);
        g_tok[i2 * NT + q2] = t; g_wt[i2 * NT + q2] = w2;

        float gg = sg[0] + sg[1] + sg[2] + sg[3];
        g_gs[t] = 1.f / (1.f + expf(-gg));
    }
}

// =========================================================================================
// All GEMMs: 128x128 smem tile, BK=8, 256 threads, 8x8 microtile, double-buffered smem.
// Dual gate/up kernels fold both matrices into one 128-wide B tile (cols 0-63 gate,
// 64-127 up) so each thread's b0/b1 fragments pair gate/up for the same output column.
// =========================================================================================

#define FMA88() do { \
    float am[8] = {a0.x, a0.y, a0.z, a0.w, a1.x, a1.y, a1.z, a1.w}; \
    float bv[8] = {b0.x, b0.y, b0.z, b0.w, b1.x, b1.y, b1.z, b1.w}; \
    _Pragma("unroll") \
    for (int mi = 0; mi < 8; mi++) \
        _Pragma("unroll") \
        for (int nj = 0; nj < 8; nj++) \
            acc[mi][nj] = fmaf(am[mi], bv[nj], acc[mi][nj]); \
} while (0)

// Shared-expert GEMM1: Hs = silu(x @ Wg) * (x @ Wu).  Wg/Wu [D, FS] (N-contiguous rows).
// Output n-tile = 64 (gate+up folded into 128-wide B).
__global__ __launch_bounds__(256, 2) void sgemm1_k(const float* __restrict__ x,
                                                   const float* __restrict__ wg,
                                                   const float* __restrict__ wu) {
    const int m0 = blockIdx.x * 128;
    const int n0 = blockIdx.y * 64;
    const int tid = threadIdx.x;
    const int tx = tid & 15, ty = tid >> 4;

    __shared__ __align__(16) float As[2][8][132];
    __shared__ __align__(16) float Bs[2][8][132];

    const int ar = tid >> 1, ak = (tid & 1) * 4;      // A: row 0..127, k {0..3|4..7}
    const int bk = tid >> 5, bn = (tid & 31) * 4;     // B: k-row 0..7, n 0..124

    const float* Ap = x + (size_t)(m0 + ar) * DD + ak;
    const float* Bp = (bn < 64) ? (wg + (size_t)bk * FSH + n0 + bn)
                                : (wu + (size_t)bk * FSH + n0 + bn - 64);

    float4 pa = *(const float4*)(Ap);
    float4 pb = *(const float4*)(Bp);
    As[0][ak + 0][ar] = pa.x; As[0][ak + 1][ar] = pa.y;
    As[0][ak + 2][ar] = pa.z; As[0][ak + 3][ar] = pa.w;
    *(float4*)&Bs[0][bk][bn] = pb;
    __syncthreads();

    float acc[8][8] = {};
    const int NKT = DD / 8;
    for (int kt = 0; kt < NKT; kt++) {
        const int buf = kt & 1;
        if (kt + 1 < NKT) {
            pa = *(const float4*)(Ap + (kt + 1) * 8);
            pb = *(const float4*)(Bp + (size_t)(kt + 1) * 8 * FSH);
        }
#pragma unroll
        for (int k = 0; k < 8; k++) {
            float4 a0 = *(const float4*)&As[buf][k][ty * 4];
            float4 a1 = *(const float4*)&As[buf][k][64 + ty * 4];
            float4 b0 = *(const float4*)&Bs[buf][k][tx * 4];
            float4 b1 = *(const float4*)&Bs[buf][k][64 + tx * 4];
            FMA88();
        }
        if (kt + 1 < NKT) {
            const int nb = buf ^ 1;
            As[nb][ak + 0][ar] = pa.x; As[nb][ak + 1][ar] = pa.y;
            As[nb][ak + 2][ar] = pa.z; As[nb][ak + 3][ar] = pa.w;
            *(float4*)&Bs[nb][bk][bn] = pb;
            __syncthreads();
        }
    }
#pragma unroll
    for (int mi = 0; mi < 8; mi++) {
        int m = m0 + ((mi < 4) ? (ty * 4 + mi) : (64 + ty * 4 + mi - 4));
        float4 r;
        float* hr = g_Hs + (size_t)m * FSH + n0 + tx * 4;
        r.x = acc[mi][0] / (1.f + expf(-acc[mi][0])) * acc[mi][4];
        r.y = acc[mi][1] / (1.f + expf(-acc[mi][1])) * acc[mi][5];
        r.z = acc[mi][2] / (1.f + expf(-acc[mi][2])) * acc[mi][6];
        r.w = acc[mi][3] / (1.f + expf(-acc[mi][3])) * acc[mi][7];
        *(float4*)hr = r;
    }
}

// Expert GEMM1 (gathered A, K-contiguous B rows): hidden -> g_H. Output f-tile = 64.
__global__ __launch_bounds__(256, 2) void egemm1_k(const float* __restrict__ x,
                                                   const float* __restrict__ gup) {
    const int e  = blockIdx.z;
    const int ne = g_cnt[e];
    const int m0 = blockIdx.x * 128;
    if (m0 >= ne) return;
    const int f0 = blockIdx.y * 64;
    const int tid = threadIdx.x;
    const int tx = tid & 15, ty = tid >> 4;

    __shared__ __align__(16) float As[2][8][132];
    __shared__ __align__(16) float Bs[2][8][132];
    __shared__ int toks[128];

    if (tid < 128) {
        int m = m0 + tid;
        toks[tid] = (m < ne) ? g_tok[e * NT + m] : -1;
    }
    __syncthreads();

    const int ar = tid >> 1, ak = (tid & 1) * 4;
    const int br = tid >> 1, bk = (tid & 1) * 4;

    const int tokm = toks[ar];
    const float* base = gup + (size_t)e * (2 * FF) * DD;
    const int brow = (br < 64) ? (f0 + br) : (FF + f0 + br - 64);
    const float* Ap = x + (size_t)((tokm >= 0) ? tokm : 0) * DD + ak;
    const float* Bp = base + (size_t)brow * DD + bk;

    float4 z4 = make_float4(0.f, 0.f, 0.f, 0.f);
    float4 pa = (tokm >= 0) ? *(const float4*)(Ap) : z4;
    float4 pb = *(const float4*)(Bp);
    As[0][ak + 0][ar] = pa.x; As[0][ak + 1][ar] = pa.y;
    As[0][ak + 2][ar] = pa.z; As[0][ak + 3][ar] = pa.w;
    Bs[0][bk + 0][br] = pb.x; Bs[0][bk + 1][br] = pb.y;
    Bs[0][bk + 2][br] = pb.z; Bs[0][bk + 3][br] = pb.w;
    __syncthreads();

    float acc[8][8] = {};
    const int NKT = DD / 8;
    for (int kt = 0; kt < NKT; kt++) {
        const int buf = kt & 1;
        if (kt + 1 < NKT) {
            pa = (tokm >= 0) ? *(const float4*)(Ap + (kt + 1) * 8) : z4;
            pb = *(const float4*)(Bp + (kt + 1) * 8);
        }
#pragma unroll
        for (int k = 0; k < 8; k++) {
            float4 a0 = *(const float4*)&As[buf][k][ty * 4];
            float4 a1 = *(const float4*)&As[buf][k][64 + ty * 4];
            float4 b0 = *(const float4*)&Bs[buf][k][tx * 4];
            float4 b1 = *(const float4*)&Bs[buf][k][64 + tx * 4];
            FMA88();
        }
        if (kt + 1 < NKT) {
            const int nb = buf ^ 1;
            As[nb][ak + 0][ar] = pa.x; As[nb][ak + 1][ar] = pa.y;
            As[nb][ak + 2][ar] = pa.z; As[nb][ak + 3][ar] = pa.w;
            Bs[nb][bk + 0][br] = pb.x; Bs[nb][bk + 1][br] = pb.y;
            Bs[nb][bk + 2][br] = pb.z; Bs[nb][bk + 3][br] = pb.w;
            __syncthreads();
        }
    }
#pragma unroll
    for (int mi = 0; mi < 8; mi++) {
        int idx = m0 + ((mi < 4) ? (ty * 4 + mi) : (64 + ty * 4 + mi - 4));
        if (idx < ne) {
            float* hr = g_H + ((size_t)e * NT + idx) * FF + f0 + tx * 4;
            float4 r;
            r.x = acc[mi][0] / (1.f + expf(-acc[mi][0])) * acc[mi][4];
            r.y = acc[mi][1] / (1.f + expf(-acc[mi][1])) * acc[mi][5];
            r.z = acc[mi][2] / (1.f + expf(-acc[mi][2])) * acc[mi][6];
            r.w = acc[mi][3] / (1.f + expf(-acc[mi][3])) * acc[mi][7];
            *(float4*)hr = r;
        }
    }
}

// Shared-expert GEMM2: out[t,d] = gate[t] * (Hs @ Wd).  Wd [FS, D] (N-contiguous rows).
// 128x128 output tile. Plain float4 stores (initializes out before expert scatter-adds).
__global__ __launch_bounds__(256, 2) void sgemm2_k(const float* __restrict__ wd,
                                                   float* __restrict__ out) {
    const int m0 = blockIdx.x * 128;
    const int n0 = blockIdx.y * 128;
    const int tid = threadIdx.x;
    const int tx = tid & 15, ty = tid >> 4;

    __shared__ __align__(16) float As[2][8][132];
    __shared__ __align__(16) float Bs[2][8][132];

    const int ar = tid >> 1, ak = (tid & 1) * 4;
    const int bk = tid >> 5, bn = (tid & 31) * 4;

    const float* Ap = g_Hs + (size_t)(m0 + ar) * FSH + ak;
    const float* Bp = wd + (size_t)bk * DD + n0 + bn;

    float4 pa = *(const float4*)(Ap);
    float4 pb = *(const float4*)(Bp);
    As[0][ak + 0][ar] = pa.x; As[0][ak + 1][ar] = pa.y;
    As[0][ak + 2][ar] = pa.z; As[0][ak + 3][ar] = pa.w;
    *(float4*)&Bs[0][bk][bn] = pb;
    __syncthreads();

    float acc[8][8] = {};
    const int NKT = FSH / 8;
    for (int kt = 0; kt < NKT; kt++) {
        const int buf = kt & 1;
        if (kt + 1 < NKT) {
            pa = *(const float4*)(Ap + (kt + 1) * 8);
            pb = *(const float4*)(Bp + (size_t)(kt + 1) * 8 * DD);
        }
#pragma unroll
        for (int k = 0; k < 8; k++) {
            float4 a0 = *(const float4*)&As[buf][k][ty * 4];
            float4 a1 = *(const float4*)&As[buf][k][64 + ty * 4];
            float4 b0 = *(const float4*)&Bs[buf][k][tx * 4];
            float4 b1 = *(const float4*)&Bs[buf][k][64 + tx * 4];
            FMA88();
        }
        if (kt + 1 < NKT) {
            const int nb = buf ^ 1;
            As[nb][ak + 0][ar] = pa.x; As[nb][ak + 1][ar] = pa.y;
            As[nb][ak + 2][ar] = pa.z; As[nb][ak + 3][ar] = pa.w;
            *(float4*)&Bs[nb][bk][bn] = pb;
            __syncthreads();
        }
    }
#pragma unroll
    for (int mi = 0; mi < 8; mi++) {
        int m = m0 + ((mi < 4) ? (ty * 4 + mi) : (64 + ty * 4 + mi - 4));
        float gs = g_gs[m];
        float* orow = out + (size_t)m * DD + n0;
        float4 r0 = make_float4(gs * acc[mi][0], gs * acc[mi][1], gs * acc[mi][2], gs * acc[mi][3]);
        float4 r1 = make_float4(gs * acc[mi][4], gs * acc[mi][5], gs * acc[mi][6], gs * acc[mi][7]);
        *(float4*)&orow[tx * 4]      = r0;
        *(float4*)&orow[64 + tx * 4] = r1;
    }
}

// Expert GEMM2: out += w_token * (H_e @ Wd_e^T). down_proj[e] [D, F] K-contiguous rows.
__global__ __launch_bounds__(256, 2) void egemm2_k(const float* __restrict__ wd,
                                                   float* __restrict__ out) {
    const int e  = blockIdx.z;
    const int ne = g_cnt[e];
    const int m0 = blockIdx.x * 128;
    if (m0 >= ne) return;
    const int d0 = blockIdx.y * 128;
    const int tid = threadIdx.x;
    const int tx = tid & 15, ty = tid >> 4;

    __shared__ __align__(16) float As[2][8][132];
    __shared__ __align__(16) float Bs[2][8][132];

    const int ar = tid >> 1, ak = (tid & 1) * 4;
    const int br = tid >> 1, bk = (tid & 1) * 4;

    // rows >= ne read garbage from g_H scratch but are masked in the epilogue.
    const int arow = (m0 + ar < ne) ? (m0 + ar) : 0;
    const float* Ap = g_H + ((size_t)e * NT + arow) * FF + ak;
    const float* Bp = wd + (size_t)e * DD * FF + (size_t)(d0 + br) * FF + bk;

    float4 pa = *(const float4*)(Ap);
    float4 pb = *(const float4*)(Bp);
    As[0][ak + 0][ar] = pa.x; As[0][ak + 1][ar] = pa.y;
    As[0][ak + 2][ar] = pa.z; As[0][ak + 3][ar] = pa.w;
    Bs[0][bk + 0][br] = pb.x; Bs[0][bk + 1][br] = pb.y;
    Bs[0][bk + 2][br] = pb.z; Bs[0][bk + 3][br] = pb.w;
    __syncthreads();

    float acc[8][8] = {};
    const int NKT = FF / 8;
    for (int kt = 0; kt < NKT; kt++) {
        const int buf = kt & 1;
        if (kt + 1 < NKT) {
            pa = *(const float4*)(Ap + (kt + 1) * 8);
            pb = *(const float4*)(Bp + (kt + 1) * 8);
        }
#pragma unroll
        for (int k = 0; k < 8; k++) {
            float4 a0 = *(const float4*)&As[buf][k][ty * 4];
            float4 a1 = *(const float4*)&As[buf][k][64 + ty * 4];
            float4 b0 = *(const float4*)&Bs[buf][k][tx * 4];
            float4 b1 = *(const float4*)&Bs[buf][k][64 + tx * 4];
            FMA88();
        }
        if (kt + 1 < NKT) {
            const int nb = buf ^ 1;
            As[nb][ak + 0][ar] = pa.x; As[nb][ak + 1][ar] = pa.y;
            As[nb][ak + 2][ar] = pa.z; As[nb][ak + 3][ar] = pa.w;
            Bs[nb][bk + 0][br] = pb.x; Bs[nb][bk + 1][br] = pb.y;
            Bs[nb][bk + 2][br] = pb.z; Bs[nb][bk + 3][br] = pb.w;
            __syncthreads();
        }
    }
#pragma unroll
    for (int mi = 0; mi < 8; mi++) {
        int idx = m0 + ((mi < 4) ? (ty * 4 + mi) : (64 + ty * 4 + mi - 4));
        if (idx < ne) {
            int   t = g_tok[e * NT + idx];
            float w = g_wt[e * NT + idx];
            float* orow = out + (size_t)t * DD + d0;
#pragma unroll
            for (int j = 0; j < 4; j++) {
                atomicAdd(&orow[tx * 4 + j],      w * acc[mi][j]);
                atomicAdd(&orow[64 + tx * 4 + j], w * acc[mi][4 + j]);
            }
        }
    }
}

__global__ void aux_k(float* __restrict__ out) {
    int e = threadIdx.x;
    float v = 0.f;
    if (e < EE) {
        float l = g_load[e] / (float)NT - 1.0f / (float)EE;
        v = l * l;
    }
#pragma unroll
    for (int off = 16; off > 0; off >>= 1)
        v += __shfl_xor_sync(0xFFFFFFFFu, v, off);
    if (threadIdx.x == 0) out[(size_t)NT * DD] = 0.001f * v;
}

// ---------------------------------------------------------------------------------------
extern "C" void kernel_launch(void* const* d_in, const int* in_sizes, int n_in,
                              void* d_out, int out_size) {
    (void)in_sizes; (void)n_in;
    const float* x     = (const float*)d_in[0];
    const float* gup   = (const float*)d_in[1];
    const float* dwn   = (const float*)d_in[2];
    const float* rw    = (const float*)d_in[3];
    const float* sgate = (const float*)d_in[4];
    const float* sup   = (const float*)d_in[5];
    const float* sdown = (const float*)d_in[6];
    const float* shg   = (const float*)d_in[7];
    float* out = (float*)d_out;

    zero_k<<<1, 32>>>();
    router_k<<<NT, 128>>>(x, rw, shg);
    sgemm1_k<<<dim3(NT / 128, FSH / 64), 256>>>(x, sgate, sup);
    sgemm2_k<<<dim3(NT / 128, DD / 128), 256>>>(sdown, out);
    egemm1_k<<<dim3(NT / 128, FF / 64, EE), 256>>>(x, gup);
    egemm2_k<<<dim3(NT / 128, DD / 128, EE), 256>>>(dwn, out);
    if (out_size > NT * DD) aux_k<<<1, 32>>>(out);
}

// round 16
// speedup vs baseline: 1.0692x; 1.0692x over previous
#include <cuda_runtime.h>
#include <cuda_bf16.h>
#include <math.h>
#include <cstdint>

#define NT   2048      // B*T tokens
#define DD   1024      // model dim
#define EE   16        // experts
#define FF   512       // expert ffn dim
#define FSH  2048      // shared expert ffn dim

#define BK     32              // k per chunk (bf16)
#define LDS    40              // smem row stride in bf16 (80B, 16B-aligned, conflict-free)
#define MAT_B  (128 * LDS * 2) // one 128xBK bf16 matrix = 10240 B
#define STG_B  (4 * MAT_B)     // AH+AL+BH+BL = 40960 B
#define SMEM_DYN (2 * STG_B + 1024)

// ---------------- scratch (static device globals; no runtime allocation) ----------------
__device__ int   g_cnt[EE];
__device__ float g_load[EE];
__device__ int   g_tok[EE * NT];
__device__ float g_wt[EE * NT];
__device__ float g_gs[NT];
__device__ float g_H[(size_t)EE * NT * FF];
__device__ float g_Hs[(size_t)NT * FSH];

// ------------------------------- helpers -----------------------------------------------
__device__ __forceinline__ uint32_t smem_u32(const void* p) {
    uint32_t a;
    asm("{ .reg .u64 t; cvta.to.shared.u64 t, %1; cvt.u32.u64 %0, t; }" : "=r"(a) : "l"(p));
    return a;
}

__device__ __forceinline__ void ldsm4(uint32_t* r, uint32_t addr) {
    asm volatile("ldmatrix.sync.aligned.m8n8.x4.shared.b16 {%0,%1,%2,%3}, [%4];"
                 : "=r"(r[0]), "=r"(r[1]), "=r"(r[2]), "=r"(r[3]) : "r"(addr));
}
__device__ __forceinline__ void ldsm2(uint32_t* r, uint32_t addr) {
    asm volatile("ldmatrix.sync.aligned.m8n8.x2.shared.b16 {%0,%1}, [%2];"
                 : "=r"(r[0]), "=r"(r[1]) : "r"(addr));
}
__device__ __forceinline__ void mma16816(float* c, const uint32_t* a, const uint32_t* b) {
    asm volatile("mma.sync.aligned.m16n8k16.row.col.f32.bf16.bf16.f32 "
                 "{%0,%1,%2,%3}, {%4,%5,%6,%7}, {%8,%9}, {%0,%1,%2,%3};"
                 : "+f"(c[0]), "+f"(c[1]), "+f"(c[2]), "+f"(c[3])
                 : "r"(a[0]), "r"(a[1]), "r"(a[2]), "r"(a[3]), "r"(b[0]), "r"(b[1]));
}

__device__ __forceinline__ void cvt_pair(float x0, float x1, uint32_t& hi, uint32_t& lo) {
    __nv_bfloat16 h0 = __float2bfloat16(x0);
    __nv_bfloat16 h1 = __float2bfloat16(x1);
    __nv_bfloat16 l0 = __float2bfloat16(x0 - __bfloat162float(h0));
    __nv_bfloat16 l1 = __float2bfloat16(x1 - __bfloat162float(h1));
    __nv_bfloat162 hh; hh.x = h0; hh.y = h1;
    __nv_bfloat162 ll; ll.x = l0; ll.y = l1;
    hi = *reinterpret_cast<uint32_t*>(&hh);
    lo = *reinterpret_cast<uint32_t*>(&ll);
}
__device__ __forceinline__ void cvt1(float x, __nv_bfloat16& h, __nv_bfloat16& l) {
    h = __float2bfloat16(x);
    l = __float2bfloat16(x - __bfloat162float(h));
}

// store one 16-element K-contiguous segment (row-major) as hi/lo bf16
__device__ __forceinline__ void st_seg16(char* th, char* tl, const float* p, int row, int colh) {
    uint32_t hi[8], lo[8];
#pragma unroll
    for (int i = 0; i < 8; i++) cvt_pair(p[2 * i], p[2 * i + 1], hi[i], lo[i]);
    uint32_t off = (uint32_t)(row * LDS + colh) * 2;
    *(uint4*)(th + off)      = make_uint4(hi[0], hi[1], hi[2], hi[3]);
    *(uint4*)(th + off + 16) = make_uint4(hi[4], hi[5], hi[6], hi[7]);
    *(uint4*)(tl + off)      = make_uint4(lo[0], lo[1], lo[2], lo[3]);
    *(uint4*)(tl + off + 16) = make_uint4(lo[4], lo[5], lo[6], lo[7]);
}
__device__ __forceinline__ void st_seg16_zero(char* th, char* tl, int row, int colh) {
    uint32_t off = (uint32_t)(row * LDS + colh) * 2;
    uint4 z = make_uint4(0u, 0u, 0u, 0u);
    *(uint4*)(th + off) = z; *(uint4*)(th + off + 16) = z;
    *(uint4*)(tl + off) = z; *(uint4*)(tl + off + 16) = z;
}

// MMA compute over one BK=32 chunk. Warp tile 32(M)x64(N).
__device__ __forceinline__ void compute_chunk(uint32_t AH, uint32_t AL, uint32_t BH, uint32_t BL,
                                              float c[2][8][4], int wm, int wn, int lane) {
#pragma unroll
    for (int ks = 0; ks < 2; ks++) {
        uint32_t ah[2][4], al[2][4];
#pragma unroll
        for (int mi = 0; mi < 2; mi++) {
            uint32_t off = (uint32_t)((wm + mi * 16 + (lane & 15)) * LDS + ks * 16 + (lane >> 4) * 8) * 2;
            ldsm4(ah[mi], AH + off);
            ldsm4(al[mi], AL + off);
        }
#pragma unroll
        for (int ni = 0; ni < 8; ni++) {
            uint32_t boff = (uint32_t)((wn + ni * 8 + (lane & 7)) * LDS + ks * 16 + ((lane >> 3) & 1) * 8) * 2;
            uint32_t bh[2], bl[2];
            ldsm2(bh, BH + boff);
            ldsm2(bl, BL + boff);
#pragma unroll
            for (int mi = 0; mi < 2; mi++) {
                mma16816(c[mi][ni], ah[mi], bh);
                mma16816(c[mi][ni], ah[mi], bl);
                mma16816(c[mi][ni], al[mi], bh);
            }
        }
    }
}

// ---------------------------------------------------------------------------------------
__global__ void zero_k() {
    int i = threadIdx.x;
    if (i < EE) { g_cnt[i] = 0; g_load[i] = 0.f; }
}

__global__ __launch_bounds__(128) void router_k(const float* __restrict__ x,
                                                const float* __restrict__ rw,
                                                const float* __restrict__ sgw) {
    const int t   = blockIdx.x;
    const int tid = threadIdx.x;
    const float* xr = x + (size_t)t * DD;

    float acc[EE];
#pragma unroll
    for (int e = 0; e < EE; e++) acc[e] = 0.f;
    float gacc = 0.f;

    for (int d = tid; d < DD; d += 128) {
        float xv = xr[d];
        const float* w = rw + (size_t)d * EE;
#pragma unroll
        for (int e = 0; e < EE; e++) acc[e] = fmaf(xv, w[e], acc[e]);
        gacc = fmaf(xv, sgw[d], gacc);
    }

#pragma unroll
    for (int off = 16; off > 0; off >>= 1) {
#pragma unroll
        for (int e = 0; e < EE; e++) acc[e] += __shfl_xor_sync(0xFFFFFFFFu, acc[e], off);
        gacc += __shfl_xor_sync(0xFFFFFFFFu, gacc, off);
    }

    __shared__ float sacc[4][EE];
    __shared__ float sg[4];
    const int w = tid >> 5, l = tid & 31;
    if (l == 0) {
#pragma unroll
        for (int e = 0; e < EE; e++) sacc[w][e] = acc[e];
        sg[w] = gacc;
    }
    __syncthreads();

    if (tid == 0) {
        float p[EE];
        float mx = -1e30f;
#pragma unroll
        for (int e = 0; e < EE; e++) {
            p[e] = sacc[0][e] + sacc[1][e] + sacc[2][e] + sacc[3][e];
            mx = fmaxf(mx, p[e]);
        }
        float s = 0.f;
#pragma unroll
        for (int e = 0; e < EE; e++) { p[e] = expf(p[e] - mx); s += p[e]; }
        float inv = 1.f / s;
#pragma unroll
        for (int e = 0; e < EE; e++) { p[e] *= inv; atomicAdd(&g_load[e], p[e]); }

        int i1 = 0;
#pragma unroll
        for (int e = 1; e < EE; e++) if (p[e] > p[i1]) i1 = e;
        int i2 = (i1 == 0) ? 1 : 0;
#pragma unroll
        for (int e = 0; e < EE; e++) if (e != i1 && p[e] > p[i2]) i2 = e;

        float ws = fmaxf(p[i1] + p[i2], 1e-9f);
        float w1 = p[i1] / ws, w2 = p[i2] / ws;

        int q1 = atomicAdd(&g_cnt[i1], 1);
        g_tok[i1 * NT + q1] = t; g_wt[i1 * NT + q1] = w1;
        int q2 = atomicAdd(&g_cnt[i2], 1);
        g_tok[i2 * NT + q2] = t; g_wt[i2 * NT + q2] = w2;

        float gg = sg[0] + sg[1] + sg[2] + sg[3];
        g_gs[t] = 1.f / (1.f + expf(-gg));
    }
}

// ================= mma.sync GEMMs: CTA 128x128, 256 thr, 8 warps (4x2) ==================
// Gate/up kernels interleave along N: col 2j = gate_j, col 2j+1 = up_j -> the (d0,d1)
// fragment pair of every thread is one (gate, up) pair for the same f.
// Single barrier per k-chunk: with 2-stage double buffering, the pre-compute barrier of
// iteration kt+1 already orders every thread's kt-compute before any kt+2 store
// (kt-compute -> kt+1-store -> kt+1-barrier in program order).

// Shared-expert GEMM1: g_Hs = silu(x@Wg)*(x@Wu); Wg/Wu [D, FS] n-contiguous.
__global__ __launch_bounds__(256) void sgemm1_k(const float* __restrict__ x,
                                                const float* __restrict__ wg,
                                                const float* __restrict__ wu) {
    extern __shared__ char dynraw[];
    char* dyn = (char*)(((uintptr_t)dynraw + 1023) & ~(uintptr_t)1023);
    const uint32_t dynu = smem_u32(dyn);

    const int tid = threadIdx.x, lane = tid & 31, warp = tid >> 5;
    const int wm = (warp >> 1) * 32, wn = (warp & 1) * 64;
    const int m0 = blockIdx.x * 128, fb = blockIdx.y * 64;

    const int arow = tid >> 1, acolh = (tid & 1) * 16;
    const float* Ap = x + (size_t)(m0 + arow) * DD + acolh;

    const int bk = tid & 31, bgrp = tid >> 5;          // k-row, f-group
    const int fl = (bgrp & 3) * 16;
    const bool isup = bgrp >= 4;
    const float* Wp = (isup ? wu : wg) + (size_t)bk * FSH + fb + fl;

    float c[2][8][4] = {};
    const int NKT = DD / BK;
    for (int kt = 0; kt < NKT; kt++) {
        char* base = dyn + (kt & 1) * STG_B;
        char* AH = base; char* AL = base + MAT_B; char* BH = base + 2 * MAT_B; char* BL = base + 3 * MAT_B;
        st_seg16(AH, AL, Ap + kt * BK, arow, acolh);
        {
            const float* src = Wp + (size_t)kt * BK * FSH;
#pragma unroll
            for (int q = 0; q < 4; q++) {
                float4 v = *(const float4*)(src + q * 4);
                float vv[4] = {v.x, v.y, v.z, v.w};
#pragma unroll
                for (int i = 0; i < 4; i++) {
                    int row = 2 * (fl + q * 4 + i) + (isup ? 1 : 0);
                    __nv_bfloat16 h, l;
                    cvt1(vv[i], h, l);
                    uint32_t off = (uint32_t)(row * LDS + bk) * 2;
                    *(__nv_bfloat16*)(BH + off) = h;
                    *(__nv_bfloat16*)(BL + off) = l;
                }
            }
        }
        __syncthreads();
        uint32_t bu = dynu + (kt & 1) * STG_B;
        compute_chunk(bu, bu + MAT_B, bu + 2 * MAT_B, bu + 3 * MAT_B, c, wm, wn, lane);
    }

#pragma unroll
    for (int mi = 0; mi < 2; mi++) {
        int r = m0 + wm + mi * 16 + (lane >> 2);
#pragma unroll
        for (int ni = 0; ni < 8; ni++) {
            int f = fb + (wn + ni * 8 + (lane & 3) * 2) / 2;
            float g0 = c[mi][ni][0], u0 = c[mi][ni][1];
            float g1 = c[mi][ni][2], u1 = c[mi][ni][3];
            g_Hs[(size_t)r * FSH + f]       = g0 / (1.f + expf(-g0)) * u0;
            g_Hs[(size_t)(r + 8) * FSH + f] = g1 / (1.f + expf(-g1)) * u1;
        }
    }
}

// Expert GEMM1: gathered A, B interleaved from gup[e] ([2F, D] K-contiguous rows).
__global__ __launch_bounds__(256) void egemm1_k(const float* __restrict__ x,
                                                const float* __restrict__ gup) {
    const int e  = blockIdx.z;
    const int ne = g_cnt[e];
    const int m0 = blockIdx.x * 128;
    if (m0 >= ne) return;
    const int fb = blockIdx.y * 64;

    extern __shared__ char dynraw[];
    char* dyn = (char*)(((uintptr_t)dynraw + 1023) & ~(uintptr_t)1023);
    const uint32_t dynu = smem_u32(dyn);
    __shared__ int toks[128];

    const int tid = threadIdx.x, lane = tid & 31, warp = tid >> 5;
    const int wm = (warp >> 1) * 32, wn = (warp & 1) * 64;

    if (tid < 128) {
        int m = m0 + tid;
        toks[tid] = (m < ne) ? g_tok[e * NT + m] : -1;
    }
    __syncthreads();

    const int arow = tid >> 1, acolh = (tid & 1) * 16;
    const int tok = toks[arow];
    const float* Ap = x + (size_t)((tok >= 0) ? tok : 0) * DD + acolh;

    const int brow = tid >> 1, bcolh = (tid & 1) * 16;
    const int srow = (brow & 1) ? (FF + fb + brow / 2) : (fb + brow / 2);
    const float* Bp = gup + (size_t)e * (2 * FF) * DD + (size_t)srow * DD + bcolh;

    float c[2][8][4] = {};
    const int NKT = DD / BK;
    for (int kt = 0; kt < NKT; kt++) {
        char* base = dyn + (kt & 1) * STG_B;
        char* AH = base; char* AL = base + MAT_B; char* BH = base + 2 * MAT_B; char* BL = base + 3 * MAT_B;
        if (tok >= 0) st_seg16(AH, AL, Ap + kt * BK, arow, acolh);
        else          st_seg16_zero(AH, AL, arow, acolh);
        st_seg16(BH, BL, Bp + kt * BK, brow, bcolh);
        __syncthreads();
        uint32_t bu = dynu + (kt & 1) * STG_B;
        compute_chunk(bu, bu + MAT_B, bu + 2 * MAT_B, bu + 3 * MAT_B, c, wm, wn, lane);
    }

#pragma unroll
    for (int mi = 0; mi < 2; mi++) {
        int r0 = wm + mi * 16 + (lane >> 2);
#pragma unroll
        for (int ni = 0; ni < 8; ni++) {
            int f = fb + (wn + ni * 8 + (lane & 3) * 2) / 2;
            float g0 = c[mi][ni][0], u0 = c[mi][ni][1];
            float g1 = c[mi][ni][2], u1 = c[mi][ni][3];
            if (m0 + r0 < ne)
                g_H[((size_t)e * NT + m0 + r0) * FF + f] = g0 / (1.f + expf(-g0)) * u0;
            if (m0 + r0 + 8 < ne)
                g_H[((size_t)e * NT + m0 + r0 + 8) * FF + f] = g1 / (1.f + expf(-g1)) * u1;
        }
    }
}

// Shared-expert GEMM2: out = g_gs[t]*(g_Hs @ Wd); Wd [FS, D] n-contiguous.
__global__ __launch_bounds__(256) void sgemm2_k(const float* __restrict__ wd,
                                                float* __restrict__ out) {
    extern __shared__ char dynraw[];
    char* dyn = (char*)(((uintptr_t)dynraw + 1023) & ~(uintptr_t)1023);
    const uint32_t dynu = smem_u32(dyn);

    const int tid = threadIdx.x, lane = tid & 31, warp = tid >> 5;
    const int wm = (warp >> 1) * 32, wn = (warp & 1) * 64;
    const int m0 = blockIdx.x * 128, n0 = blockIdx.y * 128;

    const int arow = tid >> 1, acolh = (tid & 1) * 16;
    const float* Ap = g_Hs + (size_t)(m0 + arow) * FSH + acolh;

    const int bk = tid & 31, bgrp = tid >> 5;
    const int nl = bgrp * 16;
    const float* Wp = wd + (size_t)bk * DD + n0 + nl;

    float c[2][8][4] = {};
    const int NKT = FSH / BK;
    for (int kt = 0; kt < NKT; kt++) {
        char* base = dyn + (kt & 1) * STG_B;
        char* AH = base; char* AL = base + MAT_B; char* BH = base + 2 * MAT_B; char* BL = base + 3 * MAT_B;
        st_seg16(AH, AL, Ap + kt * BK, arow, acolh);
        {
            const float* src = Wp + (size_t)kt * BK * DD;
#pragma unroll
            for (int q = 0; q < 4; q++) {
                float4 v = *(const float4*)(src + q * 4);
                float vv[4] = {v.x, v.y, v.z, v.w};
#pragma unroll
                for (int i = 0; i < 4; i++) {
                    int row = nl + q * 4 + i;
                    __nv_bfloat16 h, l;
                    cvt1(vv[i], h, l);
                    uint32_t off = (uint32_t)(row * LDS + bk) * 2;
                    *(__nv_bfloat16*)(BH + off) = h;
                    *(__nv_bfloat16*)(BL + off) = l;
                }
            }
        }
        __syncthreads();
        uint32_t bu = dynu + (kt & 1) * STG_B;
        compute_chunk(bu, bu + MAT_B, bu + 2 * MAT_B, bu + 3 * MAT_B, c, wm, wn, lane);
    }

#pragma unroll
    for (int mi = 0; mi < 2; mi++) {
        int r = m0 + wm + mi * 16 + (lane >> 2);
        float gs0 = g_gs[r], gs1 = g_gs[r + 8];
#pragma unroll
        for (int ni = 0; ni < 8; ni++) {
            int cc = n0 + wn + ni * 8 + (lane & 3) * 2;
            *(float2*)&out[(size_t)r * DD + cc]       = make_float2(gs0 * c[mi][ni][0], gs0 * c[mi][ni][1]);
            *(float2*)&out[(size_t)(r + 8) * DD + cc] = make_float2(gs1 * c[mi][ni][2], gs1 * c[mi][ni][3]);
        }
    }
}

// Expert GEMM2: out += w_tok*(g_H[e] @ dwn[e]^T); dwn[e] [D, F] K-contiguous rows.
__global__ __launch_bounds__(256) void egemm2_k(const float* __restrict__ wd,
                                                float* __restrict__ out) {
    const int e  = blockIdx.z;
    const int ne = g_cnt[e];
    const int m0 = blockIdx.x * 128;
    if (m0 >= ne) return;
    const int d0 = blockIdx.y * 128;

    extern __shared__ char dynraw[];
    char* dyn = (char*)(((uintptr_t)dynraw + 1023) & ~(uintptr_t)1023);
    const uint32_t dynu = smem_u32(dyn);

    const int tid = threadIdx.x, lane = tid & 31, warp = tid >> 5;
    const int wm = (warp >> 1) * 32, wn = (warp & 1) * 64;

    const int arow = tid >> 1, acolh = (tid & 1) * 16;
    const int ar = (m0 + arow < ne) ? (m0 + arow) : 0;
    const float* Ap = g_H + ((size_t)e * NT + ar) * FF + acolh;

    const int brow = tid >> 1, bcolh = (tid & 1) * 16;
    const float* Bp = wd + (size_t)e * DD * FF + (size_t)(d0 + brow) * FF + bcolh;

    float c[2][8][4] = {};
    const int NKT = FF / BK;
    for (int kt = 0; kt < NKT; kt++) {
        char* base = dyn + (kt & 1) * STG_B;
        char* AH = base; char* AL = base + MAT_B; char* BH = base + 2 * MAT_B; char* BL = base + 3 * MAT_B;
        st_seg16(AH, AL, Ap + kt * BK, arow, acolh);
        st_seg16(BH, BL, Bp + kt * BK, brow, bcolh);
        __syncthreads();
        uint32_t bu = dynu + (kt & 1) * STG_B;
        compute_chunk(bu, bu + MAT_B, bu + 2 * MAT_B, bu + 3 * MAT_B, c, wm, wn, lane);
    }

#pragma unroll
    for (int mi = 0; mi < 2; mi++) {
        int r0 = wm + mi * 16 + (lane >> 2);
#pragma unroll
        for (int half = 0; half < 2; half++) {
            int idx = m0 + r0 + half * 8;
            if (idx < ne) {
                const int   t = g_tok[e * NT + idx];
                const float w = g_wt[e * NT + idx];
                float* orow = out + (size_t)t * DD + d0;
#pragma unroll
                for (int ni = 0; ni < 8; ni++) {
                    int cc = wn + ni * 8 + (lane & 3) * 2;
                    atomicAdd(&orow[cc],     w * c[mi][ni][half * 2 + 0]);
                    atomicAdd(&orow[cc + 1], w * c[mi][ni][half * 2 + 1]);
                }
            }
        }
    }
}

__global__ void aux_k(float* __restrict__ out) {
    int e = threadIdx.x;
    float v = 0.f;
    if (e < EE) {
        float l = g_load[e] / (float)NT - 1.0f / (float)EE;
        v = l * l;
    }
#pragma unroll
    for (int off = 16; off > 0; off >>= 1)
        v += __shfl_xor_sync(0xFFFFFFFFu, v, off);
    if (threadIdx.x == 0) out[(size_t)NT * DD] = 0.001f * v;
}

// ---------------------------------------------------------------------------------------
extern "C" void kernel_launch(void* const* d_in, const int* in_sizes, int n_in,
                              void* d_out, int out_size) {
    (void)in_sizes; (void)n_in;
    const float* x     = (const float*)d_in[0];
    const float* gup   = (const float*)d_in[1];
    const float* dwn   = (const float*)d_in[2];
    const float* rw    = (const float*)d_in[3];
    const float* sgate = (const float*)d_in[4];
    const float* sup   = (const float*)d_in[5];
    const float* sdown = (const float*)d_in[6];
    const float* shg   = (const float*)d_in[7];
    float* out = (float*)d_out;

    cudaFuncSetAttribute(sgemm1_k, cudaFuncAttributeMaxDynamicSharedMemorySize, SMEM_DYN);
    cudaFuncSetAttribute(sgemm2_k, cudaFuncAttributeMaxDynamicSharedMemorySize, SMEM_DYN);
    cudaFuncSetAttribute(egemm1_k, cudaFuncAttributeMaxDynamicSharedMemorySize, SMEM_DYN);
    cudaFuncSetAttribute(egemm2_k, cudaFuncAttributeMaxDynamicSharedMemorySize, SMEM_DYN);

    zero_k<<<1, 32>>>();
    router_k<<<NT, 128>>>(x, rw, shg);
    sgemm1_k<<<dim3(NT / 128, FSH / 64), 256, SMEM_DYN>>>(x, sgate, sup);
    sgemm2_k<<<dim3(NT / 128, DD / 128), 256, SMEM_DYN>>>(sdown, out);
    egemm1_k<<<dim3(NT / 128, FF / 64, EE), 256, SMEM_DYN>>>(x, gup);
    egemm2_k<<<dim3(NT / 128, DD / 128, EE), 256, SMEM_DYN>>>(dwn, out);
    if (out_size > NT * DD) aux_k<<<1, 32>>>(out);
}